// round 1
// baseline (speedup 1.0000x reference)
#include <cuda_runtime.h>
#include <cstdint>
#include <cstddef>

// ---------------------------------------------------------------------------
// Problem constants
// ---------------------------------------------------------------------------
static constexpr int kT    = 512;   // timesteps
static constexpr int kB    = 64;    // batch
static constexpr int kDin  = 512;
static constexpr int kH    = 1024;
static constexpr int kDout = 512;

typedef unsigned long long ull;

// ---------------------------------------------------------------------------
// Scratch (device-global; allocation inside kernel_launch is forbidden)
// ---------------------------------------------------------------------------
__device__ float g_xh[(size_t)kT * kB * kH];   // 134 MB: input projections
__device__ float g_hs[(size_t)kT * kB * kH];   // 134 MB: hidden states per step

// ---------------------------------------------------------------------------
// f32x2 helpers (FFMA2: 2x fp32 throughput vs 3-reg FFMA on sm_103a)
// ---------------------------------------------------------------------------
__device__ __forceinline__ ull pack2(float a, float b) {
    ull r;
    asm("mov.b64 %0, {%1,%2};" : "=l"(r) : "f"(a), "f"(b));
    return r;
}
__device__ __forceinline__ void unpack2(ull v, float& a, float& b) {
    asm("mov.b64 {%0,%1}, %2;" : "=f"(a), "=f"(b) : "l"(v));
}
__device__ __forceinline__ void ffma2(ull& d, ull a, ull b) {
    asm("fma.rn.f32x2 %0, %1, %2, %3;" : "=l"(d) : "l"(a), "l"(b), "l"(d));
}

// ---------------------------------------------------------------------------
// Generic fp32 GEMM + bias:  C[M,N] = A[M,K] @ W[K,N] + bias[N]
// Tiles: 128x64x16, 256 threads, per-thread 8x4 via f32x2 pairs along N.
// M % 128 == 0, N % 64 == 0, K % 16 == 0 (holds for all our shapes).
// ---------------------------------------------------------------------------
static constexpr int GM = 128;
static constexpr int GN = 64;
static constexpr int GK = 16;

__global__ __launch_bounds__(256, 2)
void gemm_bias_kernel(const float* __restrict__ A, const float* __restrict__ W,
                      const float* __restrict__ bias, float* __restrict__ C,
                      int M, int N, int K)
{
    __shared__ float As[GK][132];   // [k][m], padded to soften transpose-store conflicts
    __shared__ float Bs[GK][GN];    // [k][n]

    const int tid = threadIdx.x;
    const int m0 = blockIdx.y * GM;
    const int n0 = blockIdx.x * GN;

    const int tn = tid & 15;   // 16 groups of 4 cols
    const int tm = tid >> 4;   // 16 groups of 8 rows

    ull acc[8][2];
#pragma unroll
    for (int i = 0; i < 8; i++) { acc[i][0] = 0ull; acc[i][1] = 0ull; }

    for (int k0 = 0; k0 < K; k0 += GK) {
        // Load A tile [128 rows][16 k] and store transposed As[k][m]
#pragma unroll
        for (int i = 0; i < 2; i++) {
            int idx = tid + i * 256;           // 512 float4 per tile
            int r = idx >> 2;                  // 0..127
            int c = idx & 3;                   // 4 float4 per row (16 k)
            float4 v = *(const float4*)(A + (size_t)(m0 + r) * K + k0 + 4 * c);
            As[4 * c + 0][r] = v.x;
            As[4 * c + 1][r] = v.y;
            As[4 * c + 2][r] = v.z;
            As[4 * c + 3][r] = v.w;
        }
        // Load B tile [16 k][64 n]
        {
            int kk = tid >> 4, c = tid & 15;
            float4 v = *(const float4*)(W + (size_t)(k0 + kk) * N + n0 + 4 * c);
            *(float4*)&Bs[kk][4 * c] = v;
        }
        __syncthreads();

#pragma unroll
        for (int kk = 0; kk < GK; kk++) {
            float4 a0 = *(const float4*)&As[kk][8 * tm];
            float4 a1 = *(const float4*)&As[kk][8 * tm + 4];
            float4 b  = *(const float4*)&Bs[kk][4 * tn];
            ull b0 = pack2(b.x, b.y);
            ull b1 = pack2(b.z, b.w);
            float av[8] = {a0.x, a0.y, a0.z, a0.w, a1.x, a1.y, a1.z, a1.w};
#pragma unroll
            for (int i = 0; i < 8; i++) {
                ull ap = pack2(av[i], av[i]);
                ffma2(acc[i][0], ap, b0);
                ffma2(acc[i][1], ap, b1);
            }
        }
        __syncthreads();
    }

    float4 bv = *(const float4*)(bias + n0 + 4 * tn);
#pragma unroll
    for (int i = 0; i < 8; i++) {
        float c0, c1, c2, c3;
        unpack2(acc[i][0], c0, c1);
        unpack2(acc[i][1], c2, c3);
        float4 o = make_float4(c0 + bv.x, c1 + bv.y, c2 + bv.z, c3 + bv.w);
        *(float4*)(C + (size_t)(m0 + 8 * tm + i) * N + n0 + 4 * tn) = o;
    }
}

// ---------------------------------------------------------------------------
// Persistent recurrence kernel: 512 steps of h = tanh(xh_t + h @ W_hh)
// Grid: 128 blocks = 4 batch-groups (16 rows) x 32 col-groups (32 cols).
// One block per SM (196 KB smem) -> all co-resident -> software grid barrier.
// W_hh slice cached in smem ONCE for all 512 steps.
// K=1024 split across two warp-pairs; f32x2 accumulators hold even/odd-k
// partials, combined at the end of each step.
// ---------------------------------------------------------------------------
static constexpr int RNB = 128;       // blocks in recurrence grid
static constexpr int SH_STRIDE = 1028; // h-tile row stride (floats): 16B-aligned, bank-staggered

__device__ unsigned int g_bar_count = 0;
__device__ unsigned int g_bar_gen   = 0;

__device__ __forceinline__ void grid_sync()
{
    __threadfence();
    __syncthreads();
    if (threadIdx.x == 0) {
        volatile unsigned int* genp = &g_bar_gen;
        unsigned int gen = *genp;
        unsigned int ticket = atomicAdd(&g_bar_count, 1u);
        if (ticket == (unsigned)(RNB - 1)) {
            g_bar_count = 0u;
            __threadfence();
            *genp = gen + 1u;
        } else {
            while (*genp == gen) { }
        }
        __threadfence();
    }
    __syncthreads();
}

__global__ __launch_bounds__(128, 1)
void rnn_steps_kernel(const float* __restrict__ xh, const float* __restrict__ h0,
                      const float* __restrict__ Whh, float* __restrict__ hs)
{
    extern __shared__ float smem[];
    float* sW = smem;                        // [512 kp][32 j][2 parity] = 32768 floats (128 KB)
    float* sH = smem + 32768;                // [16][SH_STRIDE] = 16448 floats (~64 KB)
    ull*   sC = (ull*)(smem + 32768 + 16448); // [16][32] partial pairs (4 KB)

    const int tid = threadIdx.x;
    const int jg = blockIdx.x & 31;
    const int bg = blockIdx.x >> 5;
    const int j0 = jg * 32;
    const int b0 = bg * 16;

    // --- Load W_hh[:, j0:j0+32] into smem, laid out [kpair][j][k-parity] ---
    {
        int jf  = tid & 7;    // which float4 within the 32 cols
        int kof = tid >> 3;   // 16 k-rows per pass
        for (int kb = 0; kb < kH; kb += 16) {
            int k = kb + kof;
            float4 v = *(const float4*)(Whh + (size_t)k * kH + j0 + 4 * jf);
            int kp = k >> 1, p = k & 1;
            sW[kp * 64 + (4 * jf + 0) * 2 + p] = v.x;
            sW[kp * 64 + (4 * jf + 1) * 2 + p] = v.y;
            sW[kp * 64 + (4 * jf + 2) * 2 + p] = v.z;
            sW[kp * 64 + (4 * jf + 3) * 2 + p] = v.w;
        }
    }

    const int kg  = tid >> 6;      // k-group: warps 0-1 -> k[0,512), warps 2-3 -> k[512,1024)
    const int t64 = tid & 63;
    const int tbb = t64 >> 3;      // 8 groups of 2 rows
    const int tjj = t64 & 7;       // 8 groups of 4 cols
    const int r0 = 2 * tbb;
    const int jj = 4 * tjj;

    for (int t = 0; t < kT; t++) {
        const float* hsrc = (t == 0) ? h0 : (hs + (size_t)(t - 1) * kB * kH);

        // Stage h rows b0..b0+15 into smem (coalesced float4)
#pragma unroll
        for (int i = 0; i < 32; i++) {
            int idx = tid + i * 128;    // 4096 float4
            int r  = idx >> 8;          // 256 float4 per row
            int c4 = idx & 255;
            float4 v = *(const float4*)(hsrc + (size_t)(b0 + r) * kH + 4 * c4);
            *(float4*)(sH + r * SH_STRIDE + 4 * c4) = v;
        }

        // Prefetch xh[t] for the combining half (kg==0)
        float4 x0 = make_float4(0.f, 0.f, 0.f, 0.f);
        float4 x1 = x0;
        if (kg == 0) {
            const float* xp = xh + (size_t)t * kB * kH + (size_t)(b0 + r0) * kH + j0 + jj;
            x0 = *(const float4*)xp;
            x1 = *(const float4*)(xp + kH);
        }
        __syncthreads();

        // --- Main FFMA2 loop: 256 k-pairs, 2 rows x 4 cols per thread ---
        ull a00 = 0, a01 = 0, a02 = 0, a03 = 0;
        ull a10 = 0, a11 = 0, a12 = 0, a13 = 0;
        const int kp0 = kg * 256;
        const float* h0p = sH + r0 * SH_STRIDE;
        const float* h1p = sH + (r0 + 1) * SH_STRIDE;
#pragma unroll 4
        for (int kp = kp0; kp < kp0 + 256; kp++) {
            ull hp0 = *(const ull*)(h0p + 2 * kp);
            ull hp1 = *(const ull*)(h1p + 2 * kp);
            ulonglong2 wA = *(const ulonglong2*)(sW + kp * 64 + 2 * jj);
            ulonglong2 wB = *(const ulonglong2*)(sW + kp * 64 + 2 * jj + 4);
            ffma2(a00, hp0, wA.x); ffma2(a01, hp0, wA.y);
            ffma2(a02, hp0, wB.x); ffma2(a03, hp0, wB.y);
            ffma2(a10, hp1, wA.x); ffma2(a11, hp1, wA.y);
            ffma2(a12, hp1, wB.x); ffma2(a13, hp1, wB.y);
        }

        // --- Cross-k-group reduction + tanh + store ---
        if (kg == 1) {
            ull* c = sC + (r0 * 32 + jj);
            c[0]  = a00; c[1]  = a01; c[2]  = a02; c[3]  = a03;
            c[32] = a10; c[33] = a11; c[34] = a12; c[35] = a13;
        }
        __syncthreads();
        if (kg == 0) {
            ull mine[8] = {a00, a01, a02, a03, a10, a11, a12, a13};
            const ull* c = sC + (r0 * 32 + jj);
            float xv[8] = {x0.x, x0.y, x0.z, x0.w, x1.x, x1.y, x1.z, x1.w};
            float res[8];
#pragma unroll
            for (int i = 0; i < 8; i++) {
                ull other = (i < 4) ? c[i] : c[32 + (i - 4)];
                float ml, mh, ol, oh;
                unpack2(mine[i], ml, mh);
                unpack2(other, ol, oh);
                res[i] = tanhf(xv[i] + (ml + mh) + (ol + oh));
            }
            float* dst = hs + (size_t)t * kB * kH + (size_t)(b0 + r0) * kH + j0 + jj;
            *(float4*)dst        = make_float4(res[0], res[1], res[2], res[3]);
            *(float4*)(dst + kH) = make_float4(res[4], res[5], res[6], res[7]);
        }

        if (t < kT - 1) grid_sync();
    }
}

// ---------------------------------------------------------------------------
// kernel_launch
// Inputs (metadata order): inputs, hidden, W_xh, W_hh, b_h, W_hq, b_q
// Output: outputs [T*B, D_OUT] flattened, then hidden_final [B, H] if room.
// ---------------------------------------------------------------------------
extern "C" void kernel_launch(void* const* d_in, const int* in_sizes, int n_in,
                              void* d_out, int out_size)
{
    const float* inputs = (const float*)d_in[0];
    const float* hidden = (const float*)d_in[1];
    const float* W_xh   = (const float*)d_in[2];
    const float* W_hh   = (const float*)d_in[3];
    const float* b_h    = (const float*)d_in[4];
    const float* W_hq   = (const float*)d_in[5];
    const float* b_q    = (const float*)d_in[6];
    float* out = (float*)d_out;

    float *xh = nullptr, *hs = nullptr;
    cudaGetSymbolAddress((void**)&xh, g_xh);
    cudaGetSymbolAddress((void**)&hs, g_hs);

    const int M = kT * kB;   // 32768

    // 1) xh = inputs @ W_xh + b_h   -> [32768, 1024]
    {
        dim3 grid(kH / GN, M / GM);
        gemm_bias_kernel<<<grid, 256>>>(inputs, W_xh, b_h, xh, M, kH, kDin);
    }

    // 2) persistent recurrence over 512 steps
    {
        size_t smem_bytes = (size_t)(32768 + 16448) * sizeof(float) + 512 * sizeof(ull);
        cudaFuncSetAttribute(rnn_steps_kernel,
                             cudaFuncAttributeMaxDynamicSharedMemorySize,
                             (int)smem_bytes);
        rnn_steps_kernel<<<RNB, 128, smem_bytes>>>(xh, hidden, W_hh, hs);
    }

    // 3) outputs = hs @ W_hq + b_q  -> [32768, 512]
    {
        dim3 grid(kDout / GN, M / GM);
        gemm_bias_kernel<<<grid, 256>>>(hs, W_hq, b_q, out, M, kDout, kH);
    }

    // 4) hidden_final = hs[T-1] appended after outputs (if the harness expects it)
    const long long TBO = (long long)kT * kB * kDout;   // 16,777,216
    const long long BH  = (long long)kB * kH;           // 65,536
    if ((long long)out_size >= TBO + BH) {
        cudaMemcpyAsync(out + TBO, hs + (size_t)(kT - 1) * BH,
                        (size_t)BH * sizeof(float), cudaMemcpyDeviceToDevice);
    }
}

// round 4
// speedup vs baseline: 1.8109x; 1.8109x over previous
#include <cuda_runtime.h>
#include <cstdint>
#include <cstddef>

// ---------------------------------------------------------------------------
// Problem constants
// ---------------------------------------------------------------------------
static constexpr int kT    = 512;
static constexpr int kB    = 64;
static constexpr int kDin  = 512;
static constexpr int kH    = 1024;
static constexpr int kDout = 512;

typedef unsigned long long ull;

// Scratch
__device__ float g_xh[(size_t)kT * kB * kH];
__device__ float g_hs[(size_t)kT * kB * kH];

// ---------------------------------------------------------------------------
// f32x2 helpers
// ---------------------------------------------------------------------------
__device__ __forceinline__ ull pack2(float a, float b) {
    ull r; asm("mov.b64 %0, {%1,%2};" : "=l"(r) : "f"(a), "f"(b)); return r;
}
__device__ __forceinline__ void unpack2(ull v, float& a, float& b) {
    asm("mov.b64 {%0,%1}, %2;" : "=f"(a), "=f"(b) : "l"(v));
}
__device__ __forceinline__ void ffma2(ull& d, ull a, ull b) {
    asm("fma.rn.f32x2 %0, %1, %2, %3;" : "=l"(d) : "l"(a), "l"(b), "l"(d));
}
__device__ __forceinline__ float tanh_fast(float x) {
    float r; asm("tanh.approx.f32 %0, %1;" : "=f"(r) : "f"(x)); return r;
}

// ---------------------------------------------------------------------------
// fp32 GEMM + bias (unchanged: ~734us each, 59% fma pipe)
// ---------------------------------------------------------------------------
static constexpr int GM = 128;
static constexpr int GN = 64;
static constexpr int GK = 16;

__global__ __launch_bounds__(256, 2)
void gemm_bias_kernel(const float* __restrict__ A, const float* __restrict__ W,
                      const float* __restrict__ bias, float* __restrict__ C,
                      int M, int N, int K)
{
    __shared__ float As[GK][132];
    __shared__ float Bs[GK][GN];

    const int tid = threadIdx.x;
    const int m0 = blockIdx.y * GM;
    const int n0 = blockIdx.x * GN;
    const int tn = tid & 15;
    const int tm = tid >> 4;

    ull acc[8][2];
#pragma unroll
    for (int i = 0; i < 8; i++) { acc[i][0] = 0ull; acc[i][1] = 0ull; }

    for (int k0 = 0; k0 < K; k0 += GK) {
#pragma unroll
        for (int i = 0; i < 2; i++) {
            int idx = tid + i * 256;
            int r = idx >> 2;
            int c = idx & 3;
            float4 v = *(const float4*)(A + (size_t)(m0 + r) * K + k0 + 4 * c);
            As[4 * c + 0][r] = v.x;
            As[4 * c + 1][r] = v.y;
            As[4 * c + 2][r] = v.z;
            As[4 * c + 3][r] = v.w;
        }
        {
            int kk = tid >> 4, c = tid & 15;
            float4 v = *(const float4*)(W + (size_t)(k0 + kk) * N + n0 + 4 * c);
            *(float4*)&Bs[kk][4 * c] = v;
        }
        __syncthreads();

#pragma unroll
        for (int kk = 0; kk < GK; kk++) {
            float4 a0 = *(const float4*)&As[kk][8 * tm];
            float4 a1 = *(const float4*)&As[kk][8 * tm + 4];
            float4 b  = *(const float4*)&Bs[kk][4 * tn];
            ull b0 = pack2(b.x, b.y);
            ull b1 = pack2(b.z, b.w);
            float av[8] = {a0.x, a0.y, a0.z, a0.w, a1.x, a1.y, a1.z, a1.w};
#pragma unroll
            for (int i = 0; i < 8; i++) {
                ull ap = pack2(av[i], av[i]);
                ffma2(acc[i][0], ap, b0);
                ffma2(acc[i][1], ap, b1);
            }
        }
        __syncthreads();
    }

    float4 bv = *(const float4*)(bias + n0 + 4 * tn);
#pragma unroll
    for (int i = 0; i < 8; i++) {
        float c0, c1, c2, c3;
        unpack2(acc[i][0], c0, c1);
        unpack2(acc[i][1], c2, c3);
        float4 o = make_float4(c0 + bv.x, c1 + bv.y, c2 + bv.z, c3 + bv.w);
        *(float4*)(C + (size_t)(m0 + 8 * tm + i) * N + n0 + 4 * tn) = o;
    }
}

// ---------------------------------------------------------------------------
// Recurrence: 512 steps of h = tanh(xh_t + h @ W_hh)
// 128 blocks = 4 batch-groups (16 rows) x 32 col-groups (32 cols), 256 thr.
// Each warp covers the FULL 16x32 tile (thread tile 4 rows x 4 cols,
// rows strided by 4), K split 8 ways across warps. W cached in smem once
// (bank-staggered rows), h staged row-major per step. Per-bg 32-blk barrier.
// ---------------------------------------------------------------------------
static constexpr int RNB = 128;
static constexpr int SW_KP_STRIDE = 68;    // 272 B per k-pair row
static constexpr int SH_STRIDE    = 1032;  // h row stride (floats)
static constexpr int OFF_SH = 512 * SW_KP_STRIDE;            // 34816
static constexpr int OFF_SP = OFF_SH + 16 * SH_STRIDE;       // 51328
static constexpr int SP_W_STRIDE = 536;
static constexpr int SMEM_FLOATS = OFF_SP + 8 * SP_W_STRIDE; // 55616 floats

__device__ unsigned int g_bar_cnt[4] = {0, 0, 0, 0};
__device__ unsigned int g_bar_gen[4] = {0, 0, 0, 0};

__device__ __forceinline__ void grid_sync_group(int bg)
{
    __threadfence();
    __syncthreads();
    if (threadIdx.x == 0) {
        volatile unsigned int* genp = &g_bar_gen[bg];
        unsigned int gen = *genp;
        unsigned int ticket = atomicAdd(&g_bar_cnt[bg], 1u);
        if (ticket == 31u) {
            g_bar_cnt[bg] = 0u;
            __threadfence();
            *genp = gen + 1u;
        } else {
            while (*genp == gen) { }
        }
        __threadfence();
    }
    __syncthreads();
}

__global__ __launch_bounds__(256, 1)
void rnn_steps_kernel(const float* __restrict__ xh, const float* __restrict__ h0,
                      const float* __restrict__ Whh, float* __restrict__ hs)
{
    extern __shared__ float smem[];
    float* sW = smem;
    float* sH = smem + OFF_SH;
    float* sP = smem + OFF_SP;

    const int tid  = threadIdx.x;
    const int jg   = blockIdx.x & 31;
    const int bg   = blockIdx.x >> 5;
    const int j0   = jg * 32;
    const int b0   = bg * 16;
    const int warp = tid >> 5;
    const int lane = tid & 31;
    const int rp   = lane & 3;     // row phase: rows rp, rp+4, rp+8, rp+12
    const int cp   = lane >> 2;    // col chunk 0..7: cols 4cp..4cp+3  (R3 FIX)

    // --- Load W_hh[:, j0:j0+32] into bank-staggered smem (once) ---
    // pair (k even/odd) of col j at: kp*68 + chunk*8 + (chunk>>2)*4 + (j&3)*2 + p
    {
        int jf  = tid & 7;     // chunk (4 cols)
        int kof = tid >> 3;    // 0..31
        for (int kb = 0; kb < kH; kb += 32) {
            int k  = kb + kof;
            int kp = k >> 1, p = k & 1;
            float4 v = *(const float4*)(Whh + (size_t)k * kH + j0 + 4 * jf);
            float* base = sW + kp * SW_KP_STRIDE + jf * 8 + (jf >> 2) * 4 + p;
            base[0] = v.x; base[2] = v.y; base[4] = v.z; base[6] = v.w;
        }
    }

    // reduction indices (each thread reduces outputs o=2*tid, 2*tid+1)
    const int o  = 2 * tid;
    const int rr = o >> 5;          // 0..15
    const int jl = o & 31;          // even
    const int lane_o = ((jl >> 2) << 2) + (rr & 3);
    const int i0 = ((rr >> 2) << 2) + (jl & 3);

    const int kp0 = warp * 64;
    const float* hbase = sH + rp * SH_STRIDE;
    const float* wbase = sW + cp * 8 + (cp >> 2) * 4;

    for (int t = 0; t < kT; t++) {
        const float* hsrc = (t == 0) ? h0 : (hs + (size_t)(t - 1) * kB * kH);

        // Stage h rows b0..b0+15 (coalesced float4)
#pragma unroll
        for (int i = 0; i < 16; i++) {
            int idx = tid + i * 256;     // 4096 float4
            int r   = idx >> 8;
            int c4  = idx & 255;
            float4 v = *(const float4*)(hsrc + (size_t)(b0 + r) * kH + 4 * c4);
            *(float4*)(sH + r * SH_STRIDE + 4 * c4) = v;
        }

        // Prefetch xh for this thread's two outputs
        float2 x2 = *(const float2*)(xh + ((size_t)t * kB + b0 + rr) * kH + j0 + jl);
        __syncthreads();

        // --- Main loop: 64 k-pairs, full 16x32 tile per warp ---
        ull a00 = 0, a01 = 0, a02 = 0, a03 = 0;
        ull a10 = 0, a11 = 0, a12 = 0, a13 = 0;
        ull a20 = 0, a21 = 0, a22 = 0, a23 = 0;
        ull a30 = 0, a31 = 0, a32 = 0, a33 = 0;
#pragma unroll 2
        for (int kp = kp0; kp < kp0 + 64; kp++) {
            ull h0v = *(const ull*)(hbase + 2 * kp);
            ull h1v = *(const ull*)(hbase + 4 * SH_STRIDE + 2 * kp);
            ull h2v = *(const ull*)(hbase + 8 * SH_STRIDE + 2 * kp);
            ull h3v = *(const ull*)(hbase + 12 * SH_STRIDE + 2 * kp);
            const float* wp = wbase + kp * SW_KP_STRIDE;
            ulonglong2 wA = *(const ulonglong2*)(wp);
            ulonglong2 wB = *(const ulonglong2*)(wp + 4);
            ffma2(a00, h0v, wA.x); ffma2(a01, h0v, wA.y); ffma2(a02, h0v, wB.x); ffma2(a03, h0v, wB.y);
            ffma2(a10, h1v, wA.x); ffma2(a11, h1v, wA.y); ffma2(a12, h1v, wB.x); ffma2(a13, h1v, wB.y);
            ffma2(a20, h2v, wA.x); ffma2(a21, h2v, wA.y); ffma2(a22, h2v, wB.x); ffma2(a23, h2v, wB.y);
            ffma2(a30, h3v, wA.x); ffma2(a31, h3v, wA.y); ffma2(a32, h3v, wB.x); ffma2(a33, h3v, wB.y);
        }

        // Pair-sum partials -> smem [warp][accIdx * 33 + lane]
        {
            float* myP = sP + warp * SP_W_STRIDE;
            ull av[16] = {a00, a01, a02, a03, a10, a11, a12, a13,
                          a20, a21, a22, a23, a30, a31, a32, a33};
#pragma unroll
            for (int i = 0; i < 16; i++) {
                float lo, hi; unpack2(av[i], lo, hi);
                myP[i * 33 + lane] = lo + hi;
            }
        }
        __syncthreads();

        // --- Reduce 8 warp-partials, add xh, tanh, store hs[t] ---
        {
            float s0 = 0.f, s1 = 0.f;
            const float* p0 = sP + i0 * 33 + lane_o;
#pragma unroll
            for (int w2 = 0; w2 < 8; w2++) {
                s0 += p0[w2 * SP_W_STRIDE];
                s1 += p0[w2 * SP_W_STRIDE + 33];   // accIdx i0+1 (same chunk, jl even)
            }
            float r0v = tanh_fast(x2.x + s0);
            float r1v = tanh_fast(x2.y + s1);
            float* dst = hs + (size_t)t * kB * kH + (size_t)(b0 + rr) * kH + j0 + jl;
            *(float2*)dst = make_float2(r0v, r1v);
        }

        if (t < kT - 1) grid_sync_group(bg);
    }
}

// ---------------------------------------------------------------------------
// kernel_launch
// ---------------------------------------------------------------------------
extern "C" void kernel_launch(void* const* d_in, const int* in_sizes, int n_in,
                              void* d_out, int out_size)
{
    const float* inputs = (const float*)d_in[0];
    const float* hidden = (const float*)d_in[1];
    const float* W_xh   = (const float*)d_in[2];
    const float* W_hh   = (const float*)d_in[3];
    const float* b_h    = (const float*)d_in[4];
    const float* W_hq   = (const float*)d_in[5];
    const float* b_q    = (const float*)d_in[6];
    float* out = (float*)d_out;

    float *xh = nullptr, *hs = nullptr;
    cudaGetSymbolAddress((void**)&xh, g_xh);
    cudaGetSymbolAddress((void**)&hs, g_hs);

    const int M = kT * kB;   // 32768

    // 1) xh = inputs @ W_xh + b_h
    {
        dim3 grid(kH / GN, M / GM);
        gemm_bias_kernel<<<grid, 256>>>(inputs, W_xh, b_h, xh, M, kH, kDin);
    }

    // 2) recurrence
    {
        size_t smem_bytes = (size_t)SMEM_FLOATS * sizeof(float);
        cudaFuncSetAttribute(rnn_steps_kernel,
                             cudaFuncAttributeMaxDynamicSharedMemorySize,
                             (int)smem_bytes);
        rnn_steps_kernel<<<RNB, 256, smem_bytes>>>(xh, hidden, W_hh, hs);
    }

    // 3) outputs = hs @ W_hq + b_q
    {
        dim3 grid(kDout / GN, M / GM);
        gemm_bias_kernel<<<grid, 256>>>(hs, W_hq, b_q, out, M, kDout, kH);
    }

    // 4) hidden_final appended if room
    const long long TBO = (long long)kT * kB * kDout;
    const long long BH  = (long long)kB * kH;
    if ((long long)out_size >= TBO + BH) {
        cudaMemcpyAsync(out + TBO, hs + (size_t)(kT - 1) * BH,
                        (size_t)BH * sizeof(float), cudaMemcpyDeviceToDevice);
    }
}